// round 9
// baseline (speedup 1.0000x reference)
#include <cuda_runtime.h>
#include <math.h>

#define Bnum 32
#define Tnum 2048
#define Hnum 512
#define CHUNK 16                    // t-rows per energy block (4 warps x 4 rows)
#define NCHUNK (Tnum / CHUNK)       // 128 chunks per b
#define ETHR 128                    // energy block threads

// Scratch (static device arrays — allocation-free per harness rules)
__device__ __align__(16) float g_has[Bnum * Hnum];     // ha (unscaled)
__device__ __align__(16) float g_p[Bnum * Tnum];       // unnormalized numerators
__device__ __align__(16) float g_psum[Bnum * NCHUNK];  // per-(b,chunk) partials
__device__ unsigned g_done[Bnum];                      // zero-init; reset each use

__device__ __forceinline__ float ex2a(float x) {
    float y; asm("ex2.approx.f32 %0, %1;" : "=f"(y) : "f"(x)); return y;
}
__device__ __forceinline__ float tanha(float x) {
    float y; asm("tanh.approx.f32 %0, %1;" : "=f"(y) : "f"(x)); return y;
}

#define LOG2E 1.4426950408889634f

// ---------------------------------------------------------------------------
// Kernel A: ha[b,h] = sum_k mean_L(hidden)[b,k]*Wh[h,k] + bh[h].
// Mean fused inline (hidden is 256KB, L2-resident). 64 blocks x 8 h-rows;
// warp handles 4 b x 8 h = 32 accumulators in one 16-iter k-loop.
// ---------------------------------------------------------------------------
__global__ __launch_bounds__(256) void proj_kernel(
    const float* __restrict__ hidden,
    const float* __restrict__ Wh,
    const float* __restrict__ bh)
{
    const int h0 = blockIdx.x * 8;
    __shared__ float s_w[8 * Hnum];   // 16KB
    {
        const float4* __restrict__ w4 = (const float4*)(Wh + (size_t)h0 * Hnum);
        for (int i = threadIdx.x; i < 8 * Hnum / 4; i += 256)
            ((float4*)s_w)[i] = w4[i];
    }
    __syncthreads();

    const int warp = threadIdx.x >> 5;
    const int lane = threadIdx.x & 31;
    const int b0 = warp * 4;
    const float* __restrict__ hA = hidden;                 // layer 0
    const float* __restrict__ hB = hidden + Bnum * Hnum;   // layer 1

    float acc[8][4];
    #pragma unroll
    for (int h = 0; h < 8; h++)
        #pragma unroll
        for (int j = 0; j < 4; j++) acc[h][j] = 0.f;

    #pragma unroll
    for (int k = lane; k < Hnum; k += 32) {
        float v0 = 0.5f * (hA[(b0 + 0) * Hnum + k] + hB[(b0 + 0) * Hnum + k]);
        float v1 = 0.5f * (hA[(b0 + 1) * Hnum + k] + hB[(b0 + 1) * Hnum + k]);
        float v2 = 0.5f * (hA[(b0 + 2) * Hnum + k] + hB[(b0 + 2) * Hnum + k]);
        float v3 = 0.5f * (hA[(b0 + 3) * Hnum + k] + hB[(b0 + 3) * Hnum + k]);
        #pragma unroll
        for (int h = 0; h < 8; h++) {
            float w = s_w[h * Hnum + k];
            acc[h][0] = fmaf(v0, w, acc[h][0]);
            acc[h][1] = fmaf(v1, w, acc[h][1]);
            acc[h][2] = fmaf(v2, w, acc[h][2]);
            acc[h][3] = fmaf(v3, w, acc[h][3]);
        }
    }
    #pragma unroll
    for (int h = 0; h < 8; h++)
        #pragma unroll
        for (int j = 0; j < 4; j++) {
            float a = acc[h][j];
            #pragma unroll
            for (int off = 16; off; off >>= 1)
                a += __shfl_xor_sync(0xffffffffu, a, off);
            acc[h][j] = a;
        }
    if (lane == 0) {
        #pragma unroll
        for (int h = 0; h < 8; h++) {
            float bhv = bh[h0 + h];
            #pragma unroll
            for (int j = 0; j < 4; j++)
                g_has[(b0 + j) * Hnum + h0 + h] = acc[h][j] + bhv;
        }
    }
}

// ---------------------------------------------------------------------------
// Kernel B: p[b,t] = exp( sum_h Wo[h]*tanh(eo[t,b,h]+ha[b,h]) ) for t<len,
// else 0, PLUS fused normalization via threadfence-reduction.
// FRONT-BATCHED loads: all 16 LDG.128 per warp-item issued into a register
// buffer before any consumption (MLP=16/warp), compute follows. Reg budget
// unlocked via __launch_bounds__(128, 4).
// ---------------------------------------------------------------------------
__global__ __launch_bounds__(ETHR, 4) void energy_kernel(
    const float* __restrict__ eo,
    const float* __restrict__ Wo,
    const int*   __restrict__ enc_len_w,
    float* __restrict__ out)
{
    const int b = blockIdx.x;          // b fastest -> even live-block spread
    const int chunk = blockIdx.y;
    const int tbase = chunk * CHUNK;
    // enc_len dtype auto-detect (JAX may canonicalize int64->int32):
    // lengths >= 1, so word[1]==0 iff buffer is little-endian int64.
    const bool is64 = (enc_len_w[1] == 0);
    const int len = is64 ? enc_len_w[2 * b] : enc_len_w[b];

    __shared__ __align__(16) float s_has[Hnum];
    __shared__ __align__(16) float s_wo[Hnum];
    __shared__ float s_ws[4];
    __shared__ float s_red[4];
    __shared__ float s_rinv;
    __shared__ int   s_last;

    const int tid  = threadIdx.x;
    const int warp = tid >> 5;
    const int lane = tid & 31;

    if (tbase < len) {
        {
            const float4* __restrict__ ha4 = (const float4*)(g_has + b * Hnum);
            const float4* __restrict__ wg4 = (const float4*)Wo;
            #pragma unroll
            for (int i = tid; i < Hnum / 4; i += ETHR) {
                ((float4*)s_has)[i] = ha4[i];
                ((float4*)s_wo)[i]  = wg4[i];
            }
        }
        __syncthreads();

        const float4* __restrict__ eo4 = (const float4*)eo;
        const int r0 = tbase + warp * 4;
        int nv = len - r0; nv = nv < 0 ? 0 : (nv > 4 ? 4 : nv);
        const size_t base = ((size_t)r0 * Bnum + b) * (Hnum / 4) + lane;
        const size_t tstride = (size_t)Bnum * (Hnum / 4);   // 4096 float4

        float acc0 = 0.f, acc1 = 0.f, acc2 = 0.f, acc3 = 0.f;

        if (nv == 4) {
            // ---- load phase: 16 independent LDG.128, front-batched ----
            float4 e[4][4];   // [j][r], register-resident
            #pragma unroll
            for (int j = 0; j < 4; j++) {
                const size_t off = (size_t)j * 32;
                #pragma unroll
                for (int r = 0; r < 4; r++)
                    e[j][r] = __ldcs(&eo4[base + (size_t)r * tstride + off]);
            }
            // ---- compute phase ----
            #pragma unroll
            for (int j = 0; j < 4; j++) {
                const int k4 = j * 32 + lane;
                float4 hs = ((const float4*)s_has)[k4];
                float4 wo = ((const float4*)s_wo)[k4];

                acc0 = fmaf(tanha(e[j][0].x + hs.x), wo.x, acc0);
                acc1 = fmaf(tanha(e[j][1].x + hs.x), wo.x, acc1);
                acc2 = fmaf(tanha(e[j][2].x + hs.x), wo.x, acc2);
                acc3 = fmaf(tanha(e[j][3].x + hs.x), wo.x, acc3);

                acc0 = fmaf(tanha(e[j][0].y + hs.y), wo.y, acc0);
                acc1 = fmaf(tanha(e[j][1].y + hs.y), wo.y, acc1);
                acc2 = fmaf(tanha(e[j][2].y + hs.y), wo.y, acc2);
                acc3 = fmaf(tanha(e[j][3].y + hs.y), wo.y, acc3);

                acc0 = fmaf(tanha(e[j][0].z + hs.z), wo.z, acc0);
                acc1 = fmaf(tanha(e[j][1].z + hs.z), wo.z, acc1);
                acc2 = fmaf(tanha(e[j][2].z + hs.z), wo.z, acc2);
                acc3 = fmaf(tanha(e[j][3].z + hs.z), wo.z, acc3);

                acc0 = fmaf(tanha(e[j][0].w + hs.w), wo.w, acc0);
                acc1 = fmaf(tanha(e[j][1].w + hs.w), wo.w, acc1);
                acc2 = fmaf(tanha(e[j][2].w + hs.w), wo.w, acc2);
                acc3 = fmaf(tanha(e[j][3].w + hs.w), wo.w, acc3);
            }
        } else {
            // slow path: boundary chunk, per-row guarded (rare)
            #pragma unroll
            for (int r = 0; r < 4; r++) {
                if (r < nv) {
                    float a = 0.f;
                    #pragma unroll
                    for (int j = 0; j < 4; j++) {
                        const int k4 = j * 32 + lane;
                        float4 hs = ((const float4*)s_has)[k4];
                        float4 wo = ((const float4*)s_wo)[k4];
                        float4 ev = __ldcs(&eo4[base + (size_t)r * tstride + j * 32]);
                        a = fmaf(tanha(ev.x + hs.x), wo.x, a);
                        a = fmaf(tanha(ev.y + hs.y), wo.y, a);
                        a = fmaf(tanha(ev.z + hs.z), wo.z, a);
                        a = fmaf(tanha(ev.w + hs.w), wo.w, a);
                    }
                    if (r == 0) acc0 = a; else if (r == 1) acc1 = a;
                    else if (r == 2) acc2 = a; else acc3 = a;
                }
            }
        }

        // one reduction tail for all 4 rows (independent butterflies -> ILP)
        #pragma unroll
        for (int off = 16; off; off >>= 1) {
            acc0 += __shfl_xor_sync(0xffffffffu, acc0, off);
            acc1 += __shfl_xor_sync(0xffffffffu, acc1, off);
            acc2 += __shfl_xor_sync(0xffffffffu, acc2, off);
            acc3 += __shfl_xor_sync(0xffffffffu, acc3, off);
        }
        if (lane == 0) {
            float* __restrict__ prow = &g_p[b * Tnum + r0];
            // no-max exp is safe: |energy| <= sum|Wo| ~ 18 << fp32 exp range
            float p0 = (nv > 0) ? ex2a(acc0 * LOG2E) : 0.f;
            float p1 = (nv > 1) ? ex2a(acc1 * LOG2E) : 0.f;
            float p2 = (nv > 2) ? ex2a(acc2 * LOG2E) : 0.f;
            float p3 = (nv > 3) ? ex2a(acc3 * LOG2E) : 0.f;
            prow[0] = p0; prow[1] = p1; prow[2] = p2; prow[3] = p3;
            s_ws[warp] = (p0 + p1) + (p2 + p3);
        }
        __syncthreads();
        if (tid == 0) {
            g_psum[b * NCHUNK + chunk] =
                (s_ws[0] + s_ws[1]) + (s_ws[2] + s_ws[3]);
        }
    } else {
        // fully masked chunk: zeros, no eo traffic
        if (tid < CHUNK / 4)
            ((float4*)&g_p[b * Tnum + tbase])[tid] = make_float4(0.f, 0.f, 0.f, 0.f);
        if (tid == 0) g_psum[b * NCHUNK + chunk] = 0.f;
    }

    // ---- threadfence-reduction handoff: last block of this b normalizes ----
    __threadfence();
    if (tid == 0)
        s_last = (atomicAdd(&g_done[b], 1u) == NCHUNK - 1);
    __syncthreads();
    if (!s_last) return;

    {
        float v = g_psum[b * NCHUNK + tid];   // 128 partials, 128 threads
        #pragma unroll
        for (int off = 16; off; off >>= 1)
            v += __shfl_xor_sync(0xffffffffu, v, off);
        if (lane == 0) s_red[warp] = v;
    }
    __syncthreads();
    if (tid == 0)
        s_rinv = 1.0f / ((s_red[0] + s_red[1]) + (s_red[2] + s_red[3]));
    __syncthreads();
    const float rinv = s_rinv;

    const float4* __restrict__ p4 = (const float4*)&g_p[b * Tnum];
    float4* __restrict__ o4 = (float4*)&out[b * Tnum];
    #pragma unroll
    for (int i = tid; i < Tnum / 4; i += ETHR) {
        float4 p = p4[i];
        float4 o;
        o.x = p.x * rinv; o.y = p.y * rinv; o.z = p.z * rinv; o.w = p.w * rinv;
        o4[i] = o;
    }
    if (tid == 0) g_done[b] = 0u;   // reset for next graph replay
}

// ---------------------------------------------------------------------------
extern "C" void kernel_launch(void* const* d_in, const int* in_sizes, int n_in,
                              void* d_out, int out_size)
{
    const float* hidden  = (const float*)d_in[0];      // [L,B,H]
    const float* eo      = (const float*)d_in[1];      // [T,B,H]
    const int*   enc_len = (const int*)d_in[2];        // [B] int32/int64 (auto-detect)
    const float* Wh      = (const float*)d_in[3];      // [H,H]
    const float* bh      = (const float*)d_in[4];      // [H]
    const float* Wo      = (const float*)d_in[5];      // [1,H]
    // d_in[6] = bo: uniform additive constant -> cancels in softmax, unused.
    float* out = (float*)d_out;                         // [B,T,1]

    proj_kernel<<<Hnum / 8, 256>>>(hidden, Wh, bh);
    energy_kernel<<<dim3(Bnum, NCHUNK), ETHR>>>(eo, Wo, enc_len, out);
}

// round 10
// speedup vs baseline: 1.0920x; 1.0920x over previous
#include <cuda_runtime.h>
#include <math.h>

#define Bnum 32
#define Tnum 2048
#define Hnum 512
#define CHUNK 32                    // t-rows per energy block (4 warps x 8 rows)
#define NCHUNK (Tnum / CHUNK)       // 64 chunks per b
#define ETHR 128                    // energy block threads

// Scratch (static device arrays — allocation-free per harness rules)
__device__ __align__(16) float g_has[Bnum * Hnum];     // ha (unscaled)
__device__ __align__(16) float g_p[Bnum * Tnum];       // unnormalized numerators
__device__ __align__(16) float g_psum[Bnum * NCHUNK];  // per-(b,chunk) partials
__device__ unsigned g_done[Bnum];                      // zero-init; reset each use

__device__ __forceinline__ float ex2a(float x) {
    float y; asm("ex2.approx.f32 %0, %1;" : "=f"(y) : "f"(x)); return y;
}
__device__ __forceinline__ float tanha(float x) {
    float y; asm("tanh.approx.f32 %0, %1;" : "=f"(y) : "f"(x)); return y;
}

#define LOG2E 1.4426950408889634f

// ---------------------------------------------------------------------------
// Kernel A: ha[b,h] = sum_k mean_L(hidden)[b,k]*Wh[h,k] + bh[h].
// ---------------------------------------------------------------------------
__global__ __launch_bounds__(256) void proj_kernel(
    const float* __restrict__ hidden,
    const float* __restrict__ Wh,
    const float* __restrict__ bh)
{
    const int h0 = blockIdx.x * 8;
    __shared__ float s_w[8 * Hnum];   // 16KB
    {
        const float4* __restrict__ w4 = (const float4*)(Wh + (size_t)h0 * Hnum);
        for (int i = threadIdx.x; i < 8 * Hnum / 4; i += 256)
            ((float4*)s_w)[i] = w4[i];
    }
    __syncthreads();

    const int warp = threadIdx.x >> 5;
    const int lane = threadIdx.x & 31;
    const int b0 = warp * 4;
    const float* __restrict__ hA = hidden;                 // layer 0
    const float* __restrict__ hB = hidden + Bnum * Hnum;   // layer 1

    float acc[8][4];
    #pragma unroll
    for (int h = 0; h < 8; h++)
        #pragma unroll
        for (int j = 0; j < 4; j++) acc[h][j] = 0.f;

    #pragma unroll
    for (int k = lane; k < Hnum; k += 32) {
        float v0 = 0.5f * (hA[(b0 + 0) * Hnum + k] + hB[(b0 + 0) * Hnum + k]);
        float v1 = 0.5f * (hA[(b0 + 1) * Hnum + k] + hB[(b0 + 1) * Hnum + k]);
        float v2 = 0.5f * (hA[(b0 + 2) * Hnum + k] + hB[(b0 + 2) * Hnum + k]);
        float v3 = 0.5f * (hA[(b0 + 3) * Hnum + k] + hB[(b0 + 3) * Hnum + k]);
        #pragma unroll
        for (int h = 0; h < 8; h++) {
            float w = s_w[h * Hnum + k];
            acc[h][0] = fmaf(v0, w, acc[h][0]);
            acc[h][1] = fmaf(v1, w, acc[h][1]);
            acc[h][2] = fmaf(v2, w, acc[h][2]);
            acc[h][3] = fmaf(v3, w, acc[h][3]);
        }
    }
    #pragma unroll
    for (int h = 0; h < 8; h++)
        #pragma unroll
        for (int j = 0; j < 4; j++) {
            float a = acc[h][j];
            #pragma unroll
            for (int off = 16; off; off >>= 1)
                a += __shfl_xor_sync(0xffffffffu, a, off);
            acc[h][j] = a;
        }
    if (lane == 0) {
        #pragma unroll
        for (int h = 0; h < 8; h++) {
            float bhv = bh[h0 + h];
            #pragma unroll
            for (int j = 0; j < 4; j++)
                g_has[(b0 + j) * Hnum + h0 + h] = acc[h][j] + bhv;
        }
    }
}

// ---------------------------------------------------------------------------
// Kernel B: softmax numerators with fused normalization.
// SOFTWARE PIPELINE: each warp owns 8 t-rows as 4 pairs; while computing
// pair i, pair i+1's 8 LDG.128 are in flight (double-buffered registers).
// Steady-state ~8 cache lines in flight per warp CONTINUOUSLY, which is
// what the BW x latency product needs. One deferred 8-acc reduce tail.
// ---------------------------------------------------------------------------
__global__ __launch_bounds__(ETHR, 5) void energy_kernel(
    const float* __restrict__ eo,
    const float* __restrict__ Wo,
    const int*   __restrict__ enc_len_w,
    float* __restrict__ out)
{
    const int b = blockIdx.y;
    const int chunk = blockIdx.x;
    const int tbase = chunk * CHUNK;
    // enc_len dtype auto-detect (JAX may canonicalize int64->int32):
    // lengths >= 1, so word[1]==0 iff buffer is little-endian int64.
    const bool is64 = (enc_len_w[1] == 0);
    const int len = is64 ? enc_len_w[2 * b] : enc_len_w[b];

    __shared__ __align__(16) float s_has[Hnum];
    __shared__ __align__(16) float s_wo[Hnum];
    __shared__ float s_ws[4];
    __shared__ float s_red[2];
    __shared__ float s_rinv;
    __shared__ int   s_last;

    const int tid  = threadIdx.x;
    const int warp = tid >> 5;
    const int lane = tid & 31;

    if (tbase < len) {
        {
            const float4* __restrict__ ha4 = (const float4*)(g_has + b * Hnum);
            const float4* __restrict__ wg4 = (const float4*)Wo;
            #pragma unroll
            for (int i = tid; i < Hnum / 4; i += ETHR) {
                ((float4*)s_has)[i] = ha4[i];
                ((float4*)s_wo)[i]  = wg4[i];
            }
        }
        __syncthreads();

        const float4* __restrict__ eo4 = (const float4*)eo;
        const int r0 = tbase + warp * 8;
        int nv = len - r0; nv = nv < 0 ? 0 : (nv > 8 ? 8 : nv);
        const size_t base = ((size_t)r0 * Bnum + b) * (Hnum / 4) + lane;
        const size_t ts = (size_t)Bnum * (Hnum / 4);   // row stride in float4

        float acc[8];
        #pragma unroll
        for (int r = 0; r < 8; r++) acc[r] = 0.f;

        if (nv == 8) {
            float4 bufA[8], bufB[8];   // 2 rows x 4 j each

            // prologue: load pair 0 (rows 0,1)
            #pragma unroll
            for (int j = 0; j < 4; j++) {
                bufA[j]     = __ldcs(&eo4[base + 0 * ts + (size_t)j * 32]);
                bufA[4 + j] = __ldcs(&eo4[base + 1 * ts + (size_t)j * 32]);
            }

            #pragma unroll
            for (int pr = 0; pr < 4; pr++) {
                float4* cur = (pr & 1) ? bufB : bufA;
                float4* nxt = (pr & 1) ? bufA : bufB;
                // prefetch pair pr+1 (rows 2pr+2, 2pr+3)
                if (pr < 3) {
                    #pragma unroll
                    for (int j = 0; j < 4; j++) {
                        nxt[j]     = __ldcs(&eo4[base + (size_t)(2 * pr + 2) * ts + (size_t)j * 32]);
                        nxt[4 + j] = __ldcs(&eo4[base + (size_t)(2 * pr + 3) * ts + (size_t)j * 32]);
                    }
                }
                // compute pair pr from cur
                float aA = 0.f, aB = 0.f;
                #pragma unroll
                for (int j = 0; j < 4; j++) {
                    const int k4 = j * 32 + lane;
                    float4 hs = ((const float4*)s_has)[k4];
                    float4 wo = ((const float4*)s_wo)[k4];
                    float4 eA = cur[j];
                    float4 eB = cur[4 + j];
                    aA = fmaf(tanha(eA.x + hs.x), wo.x, aA);
                    aB = fmaf(tanha(eB.x + hs.x), wo.x, aB);
                    aA = fmaf(tanha(eA.y + hs.y), wo.y, aA);
                    aB = fmaf(tanha(eB.y + hs.y), wo.y, aB);
                    aA = fmaf(tanha(eA.z + hs.z), wo.z, aA);
                    aB = fmaf(tanha(eB.z + hs.z), wo.z, aB);
                    aA = fmaf(tanha(eA.w + hs.w), wo.w, aA);
                    aB = fmaf(tanha(eB.w + hs.w), wo.w, aB);
                }
                acc[2 * pr]     = aA;
                acc[2 * pr + 1] = aB;
            }
        } else {
            // slow path: boundary chunk, per-row guarded (rare: <=1 chunk/b)
            #pragma unroll
            for (int r = 0; r < 8; r++) {
                if (r < nv) {
                    float a = 0.f;
                    #pragma unroll
                    for (int j = 0; j < 4; j++) {
                        const int k4 = j * 32 + lane;
                        float4 hs = ((const float4*)s_has)[k4];
                        float4 wo = ((const float4*)s_wo)[k4];
                        float4 ev = __ldcs(&eo4[base + (size_t)r * ts + (size_t)j * 32]);
                        a = fmaf(tanha(ev.x + hs.x), wo.x, a);
                        a = fmaf(tanha(ev.y + hs.y), wo.y, a);
                        a = fmaf(tanha(ev.z + hs.z), wo.z, a);
                        a = fmaf(tanha(ev.w + hs.w), wo.w, a);
                    }
                    acc[r] = a;
                }
            }
        }

        // one deferred reduction tail: 8 independent butterflies (ILP)
        #pragma unroll
        for (int off = 16; off; off >>= 1) {
            #pragma unroll
            for (int r = 0; r < 8; r++)
                acc[r] += __shfl_xor_sync(0xffffffffu, acc[r], off);
        }
        if (lane == 0) {
            float* __restrict__ prow = &g_p[b * Tnum + r0];
            float wsum = 0.f;
            #pragma unroll
            for (int r = 0; r < 8; r++) {
                // no-max exp is safe: |energy| <= sum|Wo| ~ 18 << fp32 range
                float p = (r < nv) ? ex2a(acc[r] * LOG2E) : 0.f;
                prow[r] = p;
                wsum += p;
            }
            s_ws[warp] = wsum;
        }
        __syncthreads();
        if (tid == 0) {
            g_psum[b * NCHUNK + chunk] =
                (s_ws[0] + s_ws[1]) + (s_ws[2] + s_ws[3]);
        }
    } else {
        // fully masked chunk: zeros, no eo traffic
        if (tid < CHUNK / 4)
            ((float4*)&g_p[b * Tnum + tbase])[tid] = make_float4(0.f, 0.f, 0.f, 0.f);
        if (tid == 0) g_psum[b * NCHUNK + chunk] = 0.f;
    }

    // ---- threadfence-reduction handoff: last block of this b normalizes ----
    __threadfence();
    if (tid == 0)
        s_last = (atomicAdd(&g_done[b], 1u) == NCHUNK - 1);
    __syncthreads();
    if (!s_last) return;

    if (tid < 64) {
        float v = g_psum[b * NCHUNK + tid];   // 64 partials
        #pragma unroll
        for (int off = 16; off; off >>= 1)
            v += __shfl_xor_sync(0xffffffffu, v, off);
        if (lane == 0) s_red[warp] = v;
    }
    __syncthreads();
    if (tid == 0) s_rinv = 1.0f / (s_red[0] + s_red[1]);
    __syncthreads();
    const float rinv = s_rinv;

    const float4* __restrict__ p4 = (const float4*)&g_p[b * Tnum];
    float4* __restrict__ o4 = (float4*)&out[b * Tnum];
    #pragma unroll
    for (int i = tid; i < Tnum / 4; i += ETHR) {
        float4 p = p4[i];
        float4 o;
        o.x = p.x * rinv; o.y = p.y * rinv; o.z = p.z * rinv; o.w = p.w * rinv;
        o4[i] = o;
    }
    if (tid == 0) g_done[b] = 0u;   // reset for next graph replay
}

// ---------------------------------------------------------------------------
extern "C" void kernel_launch(void* const* d_in, const int* in_sizes, int n_in,
                              void* d_out, int out_size)
{
    const float* hidden  = (const float*)d_in[0];      // [L,B,H]
    const float* eo      = (const float*)d_in[1];      // [T,B,H]
    const int*   enc_len = (const int*)d_in[2];        // [B] int32/int64 (auto-detect)
    const float* Wh      = (const float*)d_in[3];      // [H,H]
    const float* bh      = (const float*)d_in[4];      // [H]
    const float* Wo      = (const float*)d_in[5];      // [1,H]
    // d_in[6] = bo: uniform additive constant -> cancels in softmax, unused.
    float* out = (float*)d_out;                         // [B,T,1]

    proj_kernel<<<Hnum / 8, 256>>>(hidden, Wh, bh);
    energy_kernel<<<dim3(NCHUNK, Bnum), ETHR>>>(eo, Wo, enc_len, out);
}